// round 3
// baseline (speedup 1.0000x reference)
#include <cuda_runtime.h>
#include <cstdint>
#include <cstddef>

// Problem: B=4, S=2048 -> TOK=8192 tokens, D=512, E=32, F=512
#define TOK   8192
#define DDIM  512
#define NEXP  32

// -------------------- device scratch --------------------
__device__ float g_gate[TOK * NEXP];                         // softmax gates [t][e]
__device__ float g_wt2[(size_t)NEXP * 16 * DDIM * 32];       // [e][dc][f][dw], tf32-rounded

// -------------------- helpers --------------------
__device__ __forceinline__ uint32_t smem_u32(const void* p) {
    uint32_t a;
    asm("{ .reg .u64 t; cvta.to.shared.u64 t, %1; cvt.u32.u64 %0, t; }"
        : "=r"(a) : "l"(p));
    return a;
}
__device__ __forceinline__ uint32_t tf32r(float v) {
    uint32_t r; asm("cvt.rna.tf32.f32 %0, %1;" : "=r"(r) : "f"(v)); return r;
}
__device__ __forceinline__ void ldsm_x4(uint32_t& r0, uint32_t& r1,
                                        uint32_t& r2, uint32_t& r3, uint32_t addr) {
    asm volatile("ldmatrix.sync.aligned.m8n8.x4.shared.b16 {%0,%1,%2,%3}, [%4];"
        : "=r"(r0), "=r"(r1), "=r"(r2), "=r"(r3) : "r"(addr));
}
__device__ __forceinline__ void mma_tf32(float* c, const uint32_t* a, const uint32_t* b) {
    asm volatile(
        "mma.sync.aligned.m16n8k8.row.col.f32.tf32.tf32.f32 "
        "{%0,%1,%2,%3}, {%4,%5,%6,%7}, {%8,%9}, {%0,%1,%2,%3};"
        : "+f"(c[0]), "+f"(c[1]), "+f"(c[2]), "+f"(c[3])
        : "r"(a[0]), "r"(a[1]), "r"(a[2]), "r"(a[3]), "r"(b[0]), "r"(b[1]));
}
#define CP_ASYNC16(dst, src) \
    asm volatile("cp.async.cg.shared.global [%0], [%1], 16;" :: "r"(dst), "l"(src) : "memory")
#define CP_COMMIT() asm volatile("cp.async.commit_group;" ::: "memory")
#define CP_WAIT1()  asm volatile("cp.async.wait_group 1;" ::: "memory")
#define CP_WAIT0()  asm volatile("cp.async.wait_group 0;" ::: "memory")

// ======================== Kernel 1: gate (GEMV + softmax) ====================
// 512 blocks x 256 threads, 16 tokens/block.
// smem floats: xs[16*512]=8192, gwt[32*516]=16512, lg[16*33]=528
#define GATE_SMEM ((8192 + 16512 + 528) * 4)

__global__ void __launch_bounds__(256) gate_kernel(
    const float* __restrict__ x, const float* __restrict__ gw,
    const float* __restrict__ gb)
{
    extern __shared__ float sg[];
    float* xs  = sg;
    float* gwt = sg + 8192;
    float* lg  = sg + 8192 + 16512;
    int tid = threadIdx.x;
    int t0 = blockIdx.x * 16;

    for (int i = tid; i < 16 * DDIM; i += 256)
        xs[i] = x[(size_t)t0 * DDIM + i];
    for (int i = tid; i < DDIM * NEXP; i += 256) {
        int d = i >> 5, e = i & 31;
        gwt[e * 516 + d] = gw[i];
    }
    __syncthreads();

    int t = tid >> 4;
    int ea = (2 * tid) & 31, eb = ea + 1;
    const float4* xv = reinterpret_cast<const float4*>(xs + t * DDIM);
    const float4* wa = reinterpret_cast<const float4*>(gwt + ea * 516);
    const float4* wb = reinterpret_cast<const float4*>(gwt + eb * 516);
    float a0 = 0.f, a1 = 0.f;
    #pragma unroll 4
    for (int q = 0; q < DDIM / 4; q++) {
        float4 xq = xv[q], va = wa[q], vb = wb[q];
        a0 += xq.x * va.x + xq.y * va.y + xq.z * va.z + xq.w * va.w;
        a1 += xq.x * vb.x + xq.y * vb.y + xq.z * vb.z + xq.w * vb.w;
    }
    lg[t * 33 + ea] = a0 + gb[ea];
    lg[t * 33 + eb] = a1 + gb[eb];
    __syncthreads();

    if (tid < 16) {
        float m = -1e30f;
        #pragma unroll
        for (int e = 0; e < NEXP; e++) m = fmaxf(m, lg[tid * 33 + e]);
        float ssum = 0.f;
        #pragma unroll
        for (int e = 0; e < NEXP; e++) {
            float v = __expf(lg[tid * 33 + e] - m);
            lg[tid * 33 + e] = v;
            ssum += v;
        }
        float inv = 1.0f / ssum;
        #pragma unroll
        for (int e = 0; e < NEXP; e++)
            g_gate[(size_t)(t0 + tid) * NEXP + e] = lg[tid * 33 + e] * inv;
    }
}

// ================= Kernel 2: prepass — transpose W to [e][dc][f][dw], tf32 ===
// grid (32, 16) = (e, dc), 512 threads (thread = f). Reads coalesced along f
// for each dw; writes 128B-contiguous dw runs.
__global__ void __launch_bounds__(512) prepass_kernel(const float* __restrict__ ew)
{
    int e = blockIdx.x, dc = blockIdx.y, f = threadIdx.x;
    const float* src = ew + ((size_t)e * DDIM + dc * 32) * DDIM + f;
    uint32_t v[32];
    #pragma unroll
    for (int dw = 0; dw < 32; dw++)
        v[dw] = tf32r(src[(size_t)dw * DDIM]);
    float* dstf = g_wt2 + ((size_t)(e * 16 + dc) * DDIM + f) * 32;
    uint4* dst = reinterpret_cast<uint4*>(dstf);
    #pragma unroll
    for (int w = 0; w < 8; w++)
        dst[w] = make_uint4(v[w*4], v[w*4+1], v[w*4+2], v[w*4+3]);
}

// ======================== Kernel 3: main HMMA GEMM ==========================
// grid (4, 64): f0 = bx*128, t0 = by*128. 256 threads, 8 warps = 2(M) x 4(N),
// warp tile 64x32. K = 16384, slab = 32 k's, order k = (dc, e, dw).
// SMEM floats: Bs[3][128*36] @ 0/4608/9216, xc[128*36] @ 13824, gs[128*36] @ 18432
#define MAIN_SMEM (5 * 4608 * 4)

__global__ void __launch_bounds__(256, 1) moe_main_kernel(
    const float* __restrict__ x, float* __restrict__ out)
{
    extern __shared__ float smem[];
    uint32_t sb  = smem_u32(smem);
    uint32_t BsA = sb;                 // + buf*18432 bytes
    uint32_t xcA = sb + 3u * 18432u;
    float*   gs  = smem + 4 * 4608;

    int tid = threadIdx.x, lane = tid & 31, wid = tid >> 5;
    int wm = wid >> 2, wn = wid & 3;
    int f0 = blockIdx.x * 128, t0 = blockIdx.y * 128;

    // ---- load gate tile gs[t][e], row stride 36 floats ----
    #pragma unroll
    for (int q = 0; q < 4; q++) {
        int u = tid + 256 * q; int row = u >> 3, w = u & 7;
        float4 v = *reinterpret_cast<const float4*>(
            g_gate + (size_t)(t0 + row) * NEXP + w * 4);
        *reinterpret_cast<float4*>(gs + row * 36 + w * 4) = v;
    }

    // ---- B slab copy: wt2 block (e*16+dc), 128 rows x 128B ----
    auto issueB = [&](int s, int buf) {
        const float* srcblk = g_wt2 + (size_t)((s & 31) * 16 + (s >> 5)) * 16384;
        #pragma unroll
        for (int q = 0; q < 4; q++) {
            int u = tid + 256 * q; int row = u >> 3, w = u & 7;
            const float* src = srcblk + (f0 + row) * 32 + w * 4;
            uint32_t dst = BsA + (uint32_t)buf * 18432u
                         + (uint32_t)row * 144u + (uint32_t)w * 16u;
            CP_ASYNC16(dst, src);
        }
        CP_COMMIT();
    };

    float acc[4][4][4];
    #pragma unroll
    for (int i = 0; i < 4; i++)
        #pragma unroll
        for (int j = 0; j < 4; j++)
            #pragma unroll
            for (int r = 0; r < 4; r++) acc[i][j][r] = 0.f;

    uint32_t xf[4][4][4];   // [mfrag i][kstep][reg] — x fragments, raw f32 bits

    issueB(0, 0);
    issueB(1, 1);

    #pragma unroll 1
    for (int s = 0; s < 512; ++s) {
        int e = s & 31;
        if (e == 0) {
            int dc = s >> 5;
            __syncthreads();   // everyone done with previous xc / compute
            #pragma unroll
            for (int q = 0; q < 4; q++) {
                int u = tid + 256 * q; int row = u >> 3, w = u & 7;
                float4 v = *reinterpret_cast<const float4*>(
                    x + (size_t)(t0 + row) * DDIM + dc * 32 + w * 4);
                *reinterpret_cast<float4*>(smem + 3 * 4608 + row * 36 + w * 4) = v;
            }
            __syncthreads();
            int T = lane >> 3, r = lane & 7;
            #pragma unroll
            for (int i = 0; i < 4; i++)
                #pragma unroll
                for (int ks = 0; ks < 4; ks++) {
                    uint32_t addr = xcA
                        + (uint32_t)(wm * 64 + 16 * i + (T & 1) * 8 + r) * 144u
                        + (uint32_t)(ks * 8 + (T >> 1) * 4) * 4u;
                    ldsm_x4(xf[i][ks][0], xf[i][ks][1], xf[i][ks][2], xf[i][ks][3], addr);
                }
        }

        if (s < 510) { CP_WAIT1(); } else { CP_WAIT0(); }
        __syncthreads();                    // B[s] visible; buf[(s+2)%3] free
        if (s + 2 < 512) issueB(s + 2, (s + 2) % 3);

        // per-row gate scalars for this e
        float ge[4][2];
        #pragma unroll
        for (int i = 0; i < 4; i++)
            #pragma unroll
            for (int p = 0; p < 2; p++)
                ge[i][p] = gs[(wm * 64 + 16 * i + 8 * p + (lane >> 2)) * 36 + e];

        uint32_t bcur = BsA + (uint32_t)(s % 3) * 18432u;
        int T = lane >> 3, r = lane & 7;
        #pragma unroll
        for (int ks = 0; ks < 4; ks++) {
            uint32_t bf[4][2];
            #pragma unroll
            for (int g2 = 0; g2 < 2; g2++) {
                uint32_t addr = bcur
                    + (uint32_t)(wn * 32 + 8 * (2 * g2 + (T >> 1)) + r) * 144u
                    + (uint32_t)(ks * 8 + (T & 1) * 4) * 4u;
                ldsm_x4(bf[2*g2][0], bf[2*g2][1], bf[2*g2+1][0], bf[2*g2+1][1], addr);
            }
            #pragma unroll
            for (int i = 0; i < 4; i++) {
                uint32_t a[4];
                #pragma unroll
                for (int r2 = 0; r2 < 4; r2++)
                    a[r2] = tf32r(ge[i][r2 & 1] * __uint_as_float(xf[i][ks][r2]));
                #pragma unroll
                for (int j = 0; j < 4; j++)
                    mma_tf32(acc[i][j], a, bf[j]);
            }
        }
    }

    // ---- epilogue ----
    #pragma unroll
    for (int i = 0; i < 4; i++) {
        int row = t0 + wm * 64 + 16 * i + (lane >> 2);
        #pragma unroll
        for (int j = 0; j < 4; j++) {
            int col = f0 + wn * 32 + 8 * j + 2 * (lane & 3);
            float2 v0 = make_float2(acc[i][j][0], acc[i][j][1]);
            float2 v1 = make_float2(acc[i][j][2], acc[i][j][3]);
            *reinterpret_cast<float2*>(out + (size_t)row * DDIM + col) = v0;
            *reinterpret_cast<float2*>(out + (size_t)(row + 8) * DDIM + col) = v1;
        }
    }
}

// ======================== launch ========================
extern "C" void kernel_launch(void* const* d_in, const int* in_sizes, int n_in,
                              void* d_out, int out_size) {
    const float* x  = (const float*)d_in[0];   // [8192, 512]
    const float* gw = (const float*)d_in[1];   // [512, 32]
    const float* gb = (const float*)d_in[2];   // [32]
    const float* ew = (const float*)d_in[3];   // [32, 512, 512]
    float* out = (float*)d_out;                // [8192, 512]

    cudaFuncSetAttribute(gate_kernel,
                         cudaFuncAttributeMaxDynamicSharedMemorySize, GATE_SMEM);
    cudaFuncSetAttribute(moe_main_kernel,
                         cudaFuncAttributeMaxDynamicSharedMemorySize, MAIN_SMEM);

    gate_kernel<<<TOK / 16, 256, GATE_SMEM>>>(x, gw, gb);

    dim3 pgrid(32, 16);
    prepass_kernel<<<pgrid, 512>>>(ew);

    dim3 grid(4, 64);
    moe_main_kernel<<<grid, 256, MAIN_SMEM>>>(x, out);
}

// round 4
// speedup vs baseline: 1.0025x; 1.0025x over previous
#include <cuda_runtime.h>
#include <cstdint>
#include <cstddef>

// Problem: B=4, S=2048 -> TOK=8192 tokens, D=512, E=32, F=512
#define TOK   8192
#define DDIM  512
#define NEXP  32

// -------------------- device scratch --------------------
__device__ float g_gate[TOK * NEXP];                 // softmax gates [t][e]
// Fragment-packed W: [fblk 4][dc 16][ks 4][e 32][wn 4][lane 32][nt 4][h 2]
// value = tf32(ew[e][dc*32 + ks*8 + h*4 + lane%4][fblk*128 + wn*32 + nt*8 + lane/4])
__device__ float g_wt2[8 * 1024 * 1024 + 2048];      // 33.5MB + prefetch pad

// -------------------- helpers --------------------
__device__ __forceinline__ uint32_t smem_u32(const void* p) {
    uint32_t a;
    asm("{ .reg .u64 t; cvta.to.shared.u64 t, %1; cvt.u32.u64 %0, t; }"
        : "=r"(a) : "l"(p));
    return a;
}
__device__ __forceinline__ uint32_t tf32r(float v) {
    uint32_t r; asm("cvt.rna.tf32.f32 %0, %1;" : "=r"(r) : "f"(v)); return r;
}
__device__ __forceinline__ void ldsm_x4(uint32_t& r0, uint32_t& r1,
                                        uint32_t& r2, uint32_t& r3, uint32_t addr) {
    asm volatile("ldmatrix.sync.aligned.m8n8.x4.shared.b16 {%0,%1,%2,%3}, [%4];"
        : "=r"(r0), "=r"(r1), "=r"(r2), "=r"(r3) : "r"(addr));
}
__device__ __forceinline__ void mma_tf32(float* c, const uint32_t* a,
                                         uint32_t b0, uint32_t b1) {
    asm volatile(
        "mma.sync.aligned.m16n8k8.row.col.f32.tf32.tf32.f32 "
        "{%0,%1,%2,%3}, {%4,%5,%6,%7}, {%8,%9}, {%0,%1,%2,%3};"
        : "+f"(c[0]), "+f"(c[1]), "+f"(c[2]), "+f"(c[3])
        : "r"(a[0]), "r"(a[1]), "r"(a[2]), "r"(a[3]), "r"(b0), "r"(b1));
}

// ======================== Kernel 1: gate (GEMV + softmax) ====================
// 256 blocks x 256 threads (8 warps). Warp -> 4 tokens, lane -> expert.
// gw reads coalesced (row-major [d][e], lane = e). Warp-shuffle softmax.
#define GATE_SMEM (32 * DDIM * 4)   // x stage, 64KB

__global__ void __launch_bounds__(256) gate_kernel(
    const float* __restrict__ x, const float* __restrict__ gw,
    const float* __restrict__ gb)
{
    extern __shared__ float xs[];   // [32][512]
    int tid = threadIdx.x, lane = tid & 31, w = tid >> 5;
    int t0 = blockIdx.x * 32;

    const float4* src = reinterpret_cast<const float4*>(x + (size_t)t0 * DDIM);
    float4* dst = reinterpret_cast<float4*>(xs);
    #pragma unroll
    for (int m = 0; m < 16; m++) dst[tid + 256 * m] = src[tid + 256 * m];
    __syncthreads();

    const float* xrow = xs + w * 4 * DDIM;
    float a0 = 0.f, a1 = 0.f, a2 = 0.f, a3 = 0.f;
    #pragma unroll 4
    for (int d = 0; d < DDIM; d++) {
        float gv = __ldg(gw + d * NEXP + lane);
        a0 = fmaf(xrow[d], gv, a0);
        a1 = fmaf(xrow[DDIM + d], gv, a1);
        a2 = fmaf(xrow[2 * DDIM + d], gv, a2);
        a3 = fmaf(xrow[3 * DDIM + d], gv, a3);
    }
    float bias = __ldg(gb + lane);
    float vv[4] = {a0 + bias, a1 + bias, a2 + bias, a3 + bias};

    #pragma unroll
    for (int ti = 0; ti < 4; ti++) {
        float v = vv[ti], m = v;
        #pragma unroll
        for (int o = 16; o > 0; o >>= 1)
            m = fmaxf(m, __shfl_xor_sync(0xFFFFFFFFu, m, o));
        float p = __expf(v - m), s = p;
        #pragma unroll
        for (int o = 16; o > 0; o >>= 1)
            s += __shfl_xor_sync(0xFFFFFFFFu, s, o);
        g_gate[(size_t)(t0 + w * 4 + ti) * NEXP + lane] = p / s;
    }
}

// ================= Kernel 2: prepass — fragment-pack W, tf32 =================
// grid (32, 16) = (e, dc), 256 threads. Stage ws[32][516] (padded, conflict-free),
// scatter-gather into fragment order, coalesced 16B writes.
#define PRE_SMEM (32 * 516 * 4)   // 66048

__global__ void __launch_bounds__(256) prepass_kernel(const float* __restrict__ ew)
{
    extern __shared__ float ws[];   // [32][516]
    int tid = threadIdx.x;
    int e = blockIdx.x, dc = blockIdx.y;

    const float4* src = reinterpret_cast<const float4*>(
        ew + ((size_t)e * DDIM + dc * 32) * DDIM);
    #pragma unroll
    for (int m = 0; m < 16; m++) {
        int v = tid + 256 * m;              // 4096 float4s = 32 rows x 128 f4
        int kk = v >> 7, fq = v & 127;
        float4 t = src[v];
        *reinterpret_cast<float4*>(ws + kk * 516 + fq * 4) = t;
    }
    __syncthreads();

    #pragma unroll
    for (int m = 0; m < 16; m++) {
        int v = tid + 256 * m;              // 4096 output float4s
        int t8 = v & 1;
        int ln = (v >> 1) & 31;
        int wn = (v >> 6) & 3;
        int ks = (v >> 8) & 3;
        int fb = (v >> 10) & 3;
        int kkb = ks * 8 + (ln & 3);
        int fbase = fb * 128 + wn * 32 + (ln >> 2) + t8 * 16;  // nt0 = t8*2 -> +16
        uint4 o;
        o.x = tf32r(ws[(kkb + 0) * 516 + fbase]);
        o.y = tf32r(ws[(kkb + 4) * 516 + fbase]);
        o.z = tf32r(ws[(kkb + 0) * 516 + fbase + 8]);
        o.w = tf32r(ws[(kkb + 4) * 516 + fbase + 8]);
        size_t gdst = (((size_t)(fb * 16 + dc) * 128 + ks * 32 + e) * 256)
                    + (wn * 32 + ln) * 2 + t8;   // in float4 units
        reinterpret_cast<uint4*>(g_wt2)[gdst] = o;
    }
}

// ======================== Kernel 3: main HMMA GEMM ==========================
// grid (4 fblk, 32 tblk) = 128 CTAs (one wave). 256 threads = 8 warps,
// layout 2M x 4N, warp tile 128M x 32N; CTA tile 256M x 128N.
// B straight from gmem (fragment-packed, L2-resident), A built in registers
// from gate*x with cvt.rna, x ldmatrix'd per (dc,ks).
#define MAIN_SMEM (2 * 256 * 36 * 4)   // xs + gs, 73728

__global__ void __launch_bounds__(256, 1) moe_main_kernel(
    const float* __restrict__ x, float* __restrict__ out)
{
    extern __shared__ float smem[];
    float* xs = smem;               // [256][36]
    float* gs = smem + 256 * 36;    // [256][36]
    uint32_t xcA = smem_u32(xs);

    int tid = threadIdx.x, lane = tid & 31, wid = tid >> 5;
    int wm = wid >> 2;              // 0..1 -> 128 rows
    int wn = wid & 3;               // 0..3 -> 32 cols
    int fblk = blockIdx.x;
    int t0 = blockIdx.y * 256;
    int f0 = fblk * 128;
    int T = lane >> 3, r = lane & 7;

    // ---- stage gate tile gs[row][e] ----
    #pragma unroll
    for (int m = 0; m < 8; m++) {
        int u = tid + 256 * m;      // 2048 float4
        int row = u >> 3, wq = u & 7;
        float4 v = *reinterpret_cast<const float4*>(
            g_gate + (size_t)(t0 + row) * NEXP + wq * 4);
        *reinterpret_cast<float4*>(gs + row * 36 + wq * 4) = v;
    }

    // ---- B stream pointer (fragment-packed) ----
    const uint4* pB = reinterpret_cast<const uint4*>(g_wt2)
        + (size_t)fblk * 16 * 128 * 256 + (wn * 32 + lane) * 2;
    uint4 bn0 = pB[0], bn1 = pB[1];     // prefetch ug = 0
    uint4 bc0, bc1;

    float acc[8][4][4];
    #pragma unroll
    for (int i = 0; i < 8; i++)
        #pragma unroll
        for (int j = 0; j < 4; j++)
            #pragma unroll
            for (int q = 0; q < 4; q++) acc[i][j][q] = 0.f;

    uint32_t xf[8][4];
    uint32_t gA = smem_u32(gs) + (uint32_t)(wm * 128 + (lane >> 2)) * 144u;

    #pragma unroll 1
    for (int dc = 0; dc < 16; dc++) {
        __syncthreads();
        #pragma unroll
        for (int m = 0; m < 8; m++) {
            int u = tid + 256 * m;
            int row = u >> 3, wq = u & 7;
            float4 v = *reinterpret_cast<const float4*>(
                x + (size_t)(t0 + row) * DDIM + dc * 32 + wq * 4);
            *reinterpret_cast<float4*>(xs + row * 36 + wq * 4) = v;
        }
        __syncthreads();

        #pragma unroll 1
        for (int ks = 0; ks < 4; ks++) {
            #pragma unroll
            for (int i = 0; i < 8; i++) {
                uint32_t addr = xcA
                    + (uint32_t)(wm * 128 + 16 * i + (T & 1) * 8 + r) * 144u
                    + (uint32_t)(ks * 8 + (T >> 1) * 4) * 4u;
                ldsm_x4(xf[i][0], xf[i][1], xf[i][2], xf[i][3], addr);
            }
            #pragma unroll 1
            for (int e = 0; e < NEXP; e++) {
                bc0 = bn0; bc1 = bn1;
                pB += 256;
                bn0 = pB[0]; bn1 = pB[1];   // prefetch next (pad covers last)
                #pragma unroll
                for (int i = 0; i < 8; i++) {
                    float ge0, ge1;
                    asm("ld.shared.f32 %0, [%1];" : "=f"(ge0)
                        : "r"(gA + (uint32_t)(i * 16 * 144 + e * 4)));
                    asm("ld.shared.f32 %0, [%1];" : "=f"(ge1)
                        : "r"(gA + (uint32_t)(i * 16 * 144 + 8 * 144 + e * 4)));
                    uint32_t a[4];
                    a[0] = tf32r(ge0 * __uint_as_float(xf[i][0]));
                    a[1] = tf32r(ge1 * __uint_as_float(xf[i][1]));
                    a[2] = tf32r(ge0 * __uint_as_float(xf[i][2]));
                    a[3] = tf32r(ge1 * __uint_as_float(xf[i][3]));
                    mma_tf32(acc[i][0], a, bc0.x, bc0.y);
                    mma_tf32(acc[i][1], a, bc0.z, bc0.w);
                    mma_tf32(acc[i][2], a, bc1.x, bc1.y);
                    mma_tf32(acc[i][3], a, bc1.z, bc1.w);
                }
            }
        }
    }

    // ---- epilogue ----
    #pragma unroll
    for (int i = 0; i < 8; i++) {
        int row = t0 + wm * 128 + 16 * i + (lane >> 2);
        #pragma unroll
        for (int j = 0; j < 4; j++) {
            int col = f0 + wn * 32 + 8 * j + 2 * (lane & 3);
            *reinterpret_cast<float2*>(out + (size_t)row * DDIM + col) =
                make_float2(acc[i][j][0], acc[i][j][1]);
            *reinterpret_cast<float2*>(out + (size_t)(row + 8) * DDIM + col) =
                make_float2(acc[i][j][2], acc[i][j][3]);
        }
    }
}

// ======================== launch ========================
extern "C" void kernel_launch(void* const* d_in, const int* in_sizes, int n_in,
                              void* d_out, int out_size) {
    const float* x  = (const float*)d_in[0];   // [8192, 512]
    const float* gw = (const float*)d_in[1];   // [512, 32]
    const float* gb = (const float*)d_in[2];   // [32]
    const float* ew = (const float*)d_in[3];   // [32, 512, 512]
    float* out = (float*)d_out;                // [8192, 512]

    cudaFuncSetAttribute(gate_kernel,
                         cudaFuncAttributeMaxDynamicSharedMemorySize, GATE_SMEM);
    cudaFuncSetAttribute(prepass_kernel,
                         cudaFuncAttributeMaxDynamicSharedMemorySize, PRE_SMEM);
    cudaFuncSetAttribute(moe_main_kernel,
                         cudaFuncAttributeMaxDynamicSharedMemorySize, MAIN_SMEM);

    gate_kernel<<<TOK / 32, 256, GATE_SMEM>>>(x, gw, gb);

    dim3 pgrid(NEXP, 16);
    prepass_kernel<<<pgrid, 256, PRE_SMEM>>>(ew);

    dim3 grid(4, 32);
    moe_main_kernel<<<grid, 256, MAIN_SMEM>>>(x, out);
}

// round 5
// speedup vs baseline: 2.3017x; 2.2959x over previous
#include <cuda_runtime.h>
#include <cstdint>
#include <cstddef>

// Problem: B=4, S=2048 -> TOK=8192 tokens, D=512, E=32, F=512
#define TOK   8192
#define DDIM  512
#define NEXP  32

// -------------------- device scratch --------------------
__device__ float g_gate[TOK * NEXP];   // softmax gates [t][e]
// Fragment-packed fp16 W for mma.m16n8k16:
// u32 chunks: [fb 4][dc 16][ks2 2][e 32] -> chunk of 1024 u32:
//   [wn 4][l 2][lane 32][r 4],  u32 = {lo=W[k][f], hi=W[k+1][f]}
//   k = dc*32 + ks2*16 + 2*(lane&3) + (r&1)*8
//   f = fb*128 + wn*32 + (l*2 + (r>>1))*8 + (lane>>2)
__device__ uint32_t g_wt2h[4 * 16 * 2 * 32 * 1024 + 2048];   // 16.8MB + pad

// -------------------- helpers --------------------
__device__ __forceinline__ uint32_t smem_u32(const void* p) {
    uint32_t a;
    asm("{ .reg .u64 t; cvta.to.shared.u64 t, %1; cvt.u32.u64 %0, t; }"
        : "=r"(a) : "l"(p));
    return a;
}
// pack two f32 -> f16x2 {lo, hi}  (first src operand = hi half)
__device__ __forceinline__ uint32_t packh2(float lo, float hi) {
    uint32_t d;
    asm("cvt.rn.f16x2.f32 %0, %1, %2;" : "=r"(d) : "f"(hi), "f"(lo));
    return d;
}
__device__ __forceinline__ void mma_f16(float* c, uint32_t a0, uint32_t a1,
                                        uint32_t a2, uint32_t a3,
                                        uint32_t b0, uint32_t b1) {
    asm volatile(
        "mma.sync.aligned.m16n8k16.row.col.f32.f16.f16.f32 "
        "{%0,%1,%2,%3}, {%4,%5,%6,%7}, {%8,%9}, {%0,%1,%2,%3};"
        : "+f"(c[0]), "+f"(c[1]), "+f"(c[2]), "+f"(c[3])
        : "r"(a0), "r"(a1), "r"(a2), "r"(a3), "r"(b0), "r"(b1));
}

// ======================== Kernel 1: gate (GEMV + softmax) ====================
// 512 blocks x 256 threads, 16 tokens/block; thread = (token, expert-pair).
__global__ void __launch_bounds__(256) gate_kernel(
    const float* __restrict__ x, const float* __restrict__ gw,
    const float* __restrict__ gb)
{
    __shared__ float xs[16 * DDIM];   // 32KB
    int tid = threadIdx.x;
    int t0 = blockIdx.x * 16;
    int t = tid >> 4;
    int l16 = tid & 15;
    int e0 = l16 * 2;

    const float4* src = reinterpret_cast<const float4*>(x + (size_t)t0 * DDIM);
    float4* dst = reinterpret_cast<float4*>(xs);
    #pragma unroll
    for (int m = 0; m < 8; m++) dst[tid + 256 * m] = src[tid + 256 * m];
    __syncthreads();

    const float* xrow = xs + t * DDIM;
    const float2* gw2 = reinterpret_cast<const float2*>(gw);
    float a00 = 0.f, a01 = 0.f, a10 = 0.f, a11 = 0.f;
    #pragma unroll 4
    for (int d = 0; d < DDIM; d += 2) {
        float x0 = xrow[d], x1 = xrow[d + 1];
        float2 w0 = __ldg(gw2 + (size_t)d * 16 + l16);
        float2 w1 = __ldg(gw2 + (size_t)(d + 1) * 16 + l16);
        a00 = fmaf(x0, w0.x, a00); a01 = fmaf(x0, w0.y, a01);
        a10 = fmaf(x1, w1.x, a10); a11 = fmaf(x1, w1.y, a11);
    }
    float l0 = a00 + a10 + __ldg(gb + e0);
    float l1 = a01 + a11 + __ldg(gb + e0 + 1);

    // softmax over the 16-lane group (32 experts, 2 per lane)
    float m = fmaxf(l0, l1);
    #pragma unroll
    for (int o = 8; o > 0; o >>= 1)
        m = fmaxf(m, __shfl_xor_sync(0xFFFFFFFFu, m, o));
    float p0 = __expf(l0 - m), p1 = __expf(l1 - m);
    float s = p0 + p1;
    #pragma unroll
    for (int o = 8; o > 0; o >>= 1)
        s += __shfl_xor_sync(0xFFFFFFFFu, s, o);
    float inv = 1.0f / s;
    g_gate[(size_t)(t0 + t) * NEXP + e0]     = p0 * inv;
    g_gate[(size_t)(t0 + t) * NEXP + e0 + 1] = p1 * inv;
}

// ================= Kernel 2: prepass — fragment-pack W to fp16 ===============
// grid (32, 16) = (e, dc), 256 threads. Stage ws[32][516], emit uint4 stores.
#define PRE_SMEM (32 * 516 * 4)   // 66048

__global__ void __launch_bounds__(256) prepass_kernel(const float* __restrict__ ew)
{
    extern __shared__ float ws[];   // [32][516]
    int tid = threadIdx.x;
    int e = blockIdx.x, dc = blockIdx.y;

    const float4* src = reinterpret_cast<const float4*>(
        ew + ((size_t)e * DDIM + dc * 32) * DDIM);
    #pragma unroll
    for (int m = 0; m < 16; m++) {
        int v = tid + 256 * m;              // 4096 float4 = 32 rows x 128 f4
        int kk = v >> 7, fq = v & 127;
        float4 tv = src[v];
        *reinterpret_cast<float4*>(ws + kk * 516 + fq * 4) = tv;
    }
    __syncthreads();

    #pragma unroll
    for (int m = 0; m < 8; m++) {
        int v = tid + 256 * m;              // 2048 slots x uint4
        int lane = v & 31;
        int l    = (v >> 5) & 1;
        int wn   = (v >> 6) & 3;
        int ks2  = (v >> 8) & 1;
        int fb   = (v >> 9) & 3;
        int tig = lane & 3, gid = lane >> 2;
        uint32_t o[4];
        #pragma unroll
        for (int r = 0; r < 4; r++) {
            int k = ks2 * 16 + 2 * tig + (r & 1) * 8;     // within dc's 32
            int f = fb * 128 + wn * 32 + (l * 2 + (r >> 1)) * 8 + gid;
            o[r] = packh2(ws[k * 516 + f], ws[(k + 1) * 516 + f]);
        }
        size_t idx4 = ((((size_t)(fb * 16 + dc) * 2 + ks2) * 32 + e) * 256)
                    + wn * 64 + l * 32 + lane;
        reinterpret_cast<uint4*>(g_wt2h)[idx4] =
            make_uint4(o[0], o[1], o[2], o[3]);
    }
}

// ======================== Kernel 3: main fp16 HMMA GEMM ======================
// grid (4 fblk, 32 tblk) = 128 CTAs (one wave). 256 threads = 8 warps,
// 2(M) x 4(N), warp tile 128M x 32N; CTA tile 256M x 128N. K loop: d only
// (16 dc x 2 ks2 of k16); e is an inner accumulation sweep with gate folded
// into the register-built fp16 A fragments. B streams from L2 (16.8MB packed).
#define MAIN_SMEM (2 * 256 * 36 * 4)   // xs + gs, 73728

__global__ void __launch_bounds__(256, 1) moe_main_kernel(
    const float* __restrict__ x, float* __restrict__ out)
{
    extern __shared__ float smem[];
    float* xs = smem;               // [256][36]
    float* gs = smem + 256 * 36;    // [256][36]
    uint32_t xcA = smem_u32(xs);
    uint32_t gcA = smem_u32(gs);

    int tid = threadIdx.x, lane = tid & 31, wid = tid >> 5;
    int wm = wid >> 2;              // 0..1 -> 128 rows each
    int wn = wid & 3;               // 0..3 -> 32 cols each
    int fblk = blockIdx.x;
    int t0 = blockIdx.y * 256;
    int f0 = fblk * 128;
    int tig = lane & 3, gid = lane >> 2;

    // ---- stage gate tile gs[row][e] ----
    #pragma unroll
    for (int m = 0; m < 8; m++) {
        int u = tid + 256 * m;      // 2048 float4
        int row = u >> 3, wq = u & 7;
        float4 v = *reinterpret_cast<const float4*>(
            g_gate + (size_t)(t0 + row) * NEXP + wq * 4);
        *reinterpret_cast<float4*>(gs + row * 36 + wq * 4) = v;
    }

    // ---- B stream pointer ----
    const uint32_t* pB = g_wt2h + (size_t)fblk * (16 * 2 * 32 * 1024)
                       + wn * 256 + lane * 4;
    uint4 bn0 = *reinterpret_cast<const uint4*>(pB);
    uint4 bn1 = *reinterpret_cast<const uint4*>(pB + 128);
    uint4 bc0, bc1;

    float acc[8][4][4];
    #pragma unroll
    for (int i = 0; i < 8; i++)
        #pragma unroll
        for (int j = 0; j < 4; j++)
            #pragma unroll
            for (int q = 0; q < 4; q++) acc[i][j][q] = 0.f;

    float xf[8][8];   // per i: rows (r0,r1) x k {2tig,2tig+1,2tig+8,2tig+9}
    uint32_t gA = gcA + (uint32_t)(wm * 128 + gid) * 144u;

    #pragma unroll 1
    for (int dc = 0; dc < 16; dc++) {
        __syncthreads();
        #pragma unroll
        for (int m = 0; m < 8; m++) {
            int u = tid + 256 * m;
            int row = u >> 3, wq = u & 7;
            float4 v = *reinterpret_cast<const float4*>(
                x + (size_t)(t0 + row) * DDIM + dc * 32 + wq * 4);
            *reinterpret_cast<float4*>(xs + row * 36 + wq * 4) = v;
        }
        __syncthreads();

        #pragma unroll 1
        for (int ks2 = 0; ks2 < 2; ks2++) {
            // load x fragments (fp32) for this k16
            #pragma unroll
            for (int i = 0; i < 8; i++) {
                uint32_t a0 = xcA
                    + (uint32_t)(wm * 128 + 16 * i + gid) * 144u
                    + (uint32_t)(ks2 * 16 + 2 * tig) * 4u;
                uint32_t a1 = a0 + 8u * 144u;
                asm("ld.shared.v2.f32 {%0,%1}, [%2];"
                    : "=f"(xf[i][0]), "=f"(xf[i][1]) : "r"(a0));
                asm("ld.shared.v2.f32 {%0,%1}, [%2];"
                    : "=f"(xf[i][2]), "=f"(xf[i][3]) : "r"(a1));
                asm("ld.shared.v2.f32 {%0,%1}, [%2];"
                    : "=f"(xf[i][4]), "=f"(xf[i][5]) : "r"(a0 + 32u));
                asm("ld.shared.v2.f32 {%0,%1}, [%2];"
                    : "=f"(xf[i][6]), "=f"(xf[i][7]) : "r"(a1 + 32u));
            }

            #pragma unroll 1
            for (int e = 0; e < NEXP; e++) {
                bc0 = bn0; bc1 = bn1;
                pB += 1024;
                bn0 = *reinterpret_cast<const uint4*>(pB);         // pad covers
                bn1 = *reinterpret_cast<const uint4*>(pB + 128);   // overrun
                #pragma unroll
                for (int i = 0; i < 8; i++) {
                    float ge0, ge1;
                    asm("ld.shared.f32 %0, [%1];" : "=f"(ge0)
                        : "r"(gA + (uint32_t)(i * 16 * 144 + e * 4)));
                    asm("ld.shared.f32 %0, [%1];" : "=f"(ge1)
                        : "r"(gA + (uint32_t)(i * 16 * 144 + 8 * 144 + e * 4)));
                    uint32_t a0 = packh2(ge0 * xf[i][0], ge0 * xf[i][1]);
                    uint32_t a1 = packh2(ge1 * xf[i][2], ge1 * xf[i][3]);
                    uint32_t a2 = packh2(ge0 * xf[i][4], ge0 * xf[i][5]);
                    uint32_t a3 = packh2(ge1 * xf[i][6], ge1 * xf[i][7]);
                    mma_f16(acc[i][0], a0, a1, a2, a3, bc0.x, bc0.y);
                    mma_f16(acc[i][1], a0, a1, a2, a3, bc0.z, bc0.w);
                    mma_f16(acc[i][2], a0, a1, a2, a3, bc1.x, bc1.y);
                    mma_f16(acc[i][3], a0, a1, a2, a3, bc1.z, bc1.w);
                }
            }
        }
    }

    // ---- epilogue ----
    #pragma unroll
    for (int i = 0; i < 8; i++) {
        int row = t0 + wm * 128 + 16 * i + gid;
        #pragma unroll
        for (int j = 0; j < 4; j++) {
            int col = f0 + wn * 32 + 8 * j + 2 * (lane & 3);
            *reinterpret_cast<float2*>(out + (size_t)row * DDIM + col) =
                make_float2(acc[i][j][0], acc[i][j][1]);
            *reinterpret_cast<float2*>(out + (size_t)(row + 8) * DDIM + col) =
                make_float2(acc[i][j][2], acc[i][j][3]);
        }
    }
}

// ======================== launch ========================
extern "C" void kernel_launch(void* const* d_in, const int* in_sizes, int n_in,
                              void* d_out, int out_size) {
    const float* x  = (const float*)d_in[0];   // [8192, 512]
    const float* gw = (const float*)d_in[1];   // [512, 32]
    const float* gb = (const float*)d_in[2];   // [32]
    const float* ew = (const float*)d_in[3];   // [32, 512, 512]
    float* out = (float*)d_out;                // [8192, 512]

    cudaFuncSetAttribute(prepass_kernel,
                         cudaFuncAttributeMaxDynamicSharedMemorySize, PRE_SMEM);
    cudaFuncSetAttribute(moe_main_kernel,
                         cudaFuncAttributeMaxDynamicSharedMemorySize, MAIN_SMEM);

    gate_kernel<<<TOK / 16, 256>>>(x, gw, gb);

    dim3 pgrid(NEXP, 16);
    prepass_kernel<<<pgrid, 256, PRE_SMEM>>>(ew);

    dim3 grid(4, 32);
    moe_main_kernel<<<grid, 256, MAIN_SMEM>>>(x, out);
}